// round 17
// baseline (speedup 1.0000x reference)
#include <cuda_runtime.h>
#include <cuda_bf16.h>
#include <cstdint>

#define N_NODES 50000
#define N_EDGES 600000
#define DIM 128
#define LN_EPS 1e-5f

// ---------------- scratch (static device globals; no allocation) -------------
__device__ float4 g_agg4[N_NODES * (DIM / 4)];   // 25.6 MB aggregation buffer
__device__ float  g_deg_out[N_NODES];
__device__ int    g_deg_in[N_NODES];
__device__ float  g_norm_out[N_NODES];
__device__ float  g_norm_in[N_NODES];
__device__ int    g_start[N_NODES + 1];
__device__ int    g_cursor[N_NODES];
__device__ int    g_sorted_src[N_EDGES];
__device__ __nv_bfloat16 g_whi[256 * 128];       // W=[fc_w;res_w] hi bf16
__device__ __nv_bfloat16 g_wlo[256 * 128];       // W lo residual bf16

// ---------------- K0: zero degree counters ------------------------------------
__global__ void zero_kernel(int nN) {
    int i = blockIdx.x * blockDim.x + threadIdx.x;
    if (i < nN) { g_deg_out[i] = 0.f; g_deg_in[i] = 0; }
}

// ---------------- K0b: pre-split W into bf16 hi/lo (once) ---------------------
__global__ void wsplit_kernel(const float* __restrict__ fc_w,
                              const float* __restrict__ res_w) {
    int i = blockIdx.x * blockDim.x + threadIdx.x;   // over 8192 float4 groups
    if (i >= 8192) return;
    int k = i >> 5, j = i & 31;
    const float* Wc = (k < 128) ? (fc_w + k * 128) : (res_w + (k - 128) * 128);
    float4 wv = *reinterpret_cast<const float4*>(Wc + 4 * j);
    __nv_bfloat162 h0 = __floats2bfloat162_rn(wv.x, wv.y);
    __nv_bfloat162 h1 = __floats2bfloat162_rn(wv.z, wv.w);
    __nv_bfloat162 l0 = __floats2bfloat162_rn(wv.x - __low2float(h0),
                                              wv.y - __high2float(h0));
    __nv_bfloat162 l1 = __floats2bfloat162_rn(wv.z - __low2float(h1),
                                              wv.w - __high2float(h1));
    *reinterpret_cast<__nv_bfloat162*>(g_whi + k * 128 + 4 * j)     = h0;
    *reinterpret_cast<__nv_bfloat162*>(g_whi + k * 128 + 4 * j + 2) = h1;
    *reinterpret_cast<__nv_bfloat162*>(g_wlo + k * 128 + 4 * j)     = l0;
    *reinterpret_cast<__nv_bfloat162*>(g_wlo + k * 128 + 4 * j + 2) = l1;
}

// ---------------- K1: degrees --------------------------------------------------
__global__ void degree_kernel(const int* __restrict__ src,
                              const int* __restrict__ dst, int nE) {
    int i = blockIdx.x * blockDim.x + threadIdx.x;
    if (i < nE) {
        atomicAdd(&g_deg_out[src[i]], 1.f);
        atomicAdd(&g_deg_in[dst[i]], 1);
    }
}

// ---------------- K2: single-block exclusive scan + norms ---------------------
__global__ void __launch_bounds__(1024, 1) scan_kernel(int nN) {
    __shared__ int warp_sums[32];
    __shared__ int carry_s;
    int tid = threadIdx.x;
    int lane = tid & 31;
    int wid = tid >> 5;
    if (tid == 0) carry_s = 0;
    __syncthreads();

    for (int base = 0; base < nN; base += 1024) {
        int i = base + tid;
        int v = (i < nN) ? g_deg_in[i] : 0;
        // warp inclusive scan
        int x = v;
#pragma unroll
        for (int o = 1; o < 32; o <<= 1) {
            int y = __shfl_up_sync(0xffffffffu, x, o);
            if (lane >= o) x += y;
        }
        if (lane == 31) warp_sums[wid] = x;
        __syncthreads();
        if (tid < 32) {
            int y = warp_sums[tid];
#pragma unroll
            for (int o = 1; o < 32; o <<= 1) {
                int z = __shfl_up_sync(0xffffffffu, y, o);
                if (tid >= o) y += z;
            }
            warp_sums[tid] = y;
        }
        __syncthreads();
        int prefix = (wid > 0) ? warp_sums[wid - 1] : 0;
        int incl = x + prefix;
        int carry = carry_s;
        if (i < nN) {
            int excl = carry + incl - v;
            g_start[i] = excl;
            g_cursor[i] = excl;
            g_norm_in[i]  = rsqrtf(fmaxf((float)v, 1.f));
            g_norm_out[i] = rsqrtf(fmaxf(g_deg_out[i], 1.f));
        }
        __syncthreads();
        if (tid == 1023) carry_s = carry + incl;
        __syncthreads();
    }
    if (tid == 0) g_start[nN] = carry_s;
}

// ---------------- K3: fill sorted-by-dst edge list -----------------------------
__global__ void fill_kernel(const int* __restrict__ src,
                            const int* __restrict__ dst, int nE) {
    int i = blockIdx.x * blockDim.x + threadIdx.x;
    if (i < nE) {
        int pos = atomicAdd(&g_cursor[dst[i]], 1);
        g_sorted_src[pos] = src[i];
    }
}

// ---------------- K4: gather-aggregate (warp per dst, no atomics) -------------
__global__ void __launch_bounds__(256)
aggregate_kernel(const float* __restrict__ feat, int nN) {
    int w = (blockIdx.x * blockDim.x + threadIdx.x) >> 5;
    int lane = threadIdx.x & 31;
    if (w >= nN) return;
    int beg = __ldg(&g_start[w]);
    int end = __ldg(&g_start[w + 1]);
    float4 acc = make_float4(0.f, 0.f, 0.f, 0.f);
    const float4* f4 = reinterpret_cast<const float4*>(feat);

    for (int base = beg; base < end; base += 32) {
        int cnt = min(32, end - base);
        int sl = 0; float nl = 0.f;
        if (lane < cnt) {
            sl = __ldg(g_sorted_src + base + lane);
            nl = __ldg(&g_norm_out[sl]);
        }
        for (int j = 0; j < cnt; j++) {
            int s = __shfl_sync(0xffffffffu, sl, j);
            float ns = __shfl_sync(0xffffffffu, nl, j);
            float4 v = __ldg(f4 + (size_t)s * 32 + lane);
            acc.x = fmaf(ns, v.x, acc.x);
            acc.y = fmaf(ns, v.y, acc.y);
            acc.z = fmaf(ns, v.z, acc.z);
            acc.w = fmaf(ns, v.w, acc.w);
        }
    }
    g_agg4[(size_t)w * 32 + lane] = acc;
}

// ================= mma.sync helpers (sm_80+ HMMA) =============================
__device__ __forceinline__ uint32_t smem_u32(const void* p) {
    uint32_t a;
    asm("{ .reg .u64 t; cvta.to.shared.u64 t, %1; cvt.u32.u64 %0, t; }"
        : "=r"(a) : "l"(p));
    return a;
}
__device__ __forceinline__ void ldmx4(uint32_t r[4], uint32_t addr) {
    asm volatile("ldmatrix.sync.aligned.m8n8.x4.shared.b16 {%0,%1,%2,%3}, [%4];"
                 : "=r"(r[0]), "=r"(r[1]), "=r"(r[2]), "=r"(r[3]) : "r"(addr));
}
__device__ __forceinline__ void ldmx4t(uint32_t r[4], uint32_t addr) {
    asm volatile("ldmatrix.sync.aligned.m8n8.x4.trans.shared.b16 {%0,%1,%2,%3}, [%4];"
                 : "=r"(r[0]), "=r"(r[1]), "=r"(r[2]), "=r"(r[3]) : "r"(addr));
}
__device__ __forceinline__ void mma16816(float* d, const uint32_t* a,
                                         uint32_t b0, uint32_t b1) {
    asm volatile(
        "mma.sync.aligned.m16n8k16.row.col.f32.bf16.bf16.f32 "
        "{%0,%1,%2,%3}, {%4,%5,%6,%7}, {%8,%9}, {%0,%1,%2,%3};"
        : "+f"(d[0]), "+f"(d[1]), "+f"(d[2]), "+f"(d[3])
        : "r"(a[0]), "r"(a[1]), "r"(a[2]), "r"(a[3]), "r"(b0), "r"(b1));
}

// ---------------- K5: HMMA fused GEMM + bias/scale + LN + ReLU ----------------
// CTA = 128 nodes, 512 threads = 16 warps: warp w -> M-tile (w&7)*16 rows,
// N-half (w>>3)*64 cols. K=256 as 2 chunks of 128. bf16 hi/lo 3-term split,
// term-major MMA order. W pre-split in gmem.
#define ROWB 272
__global__ void __launch_bounds__(512, 1)
final_kernel(const float* __restrict__ feat,
             const float* __restrict__ fc_b,
             const float* __restrict__ ln_g, const float* __restrict__ ln_b,
             float* __restrict__ out, int nN) {
    extern __shared__ char sm[];
    const uint32_t OFF_AHI = 0, OFF_ALO = 34816;
    const uint32_t OFF_BHI = 69632, OFF_BLO = 104448;
    const uint32_t OFF_NRM = 139264;   // 128 floats
    const uint32_t OFF_STAT = 139776;  // 128 rows x 2 halves x float2 = 2KB
    uint32_t sbase = smem_u32(sm);
    float* inorm_s = reinterpret_cast<float*>(sm + OFF_NRM);
    float2* stat_s = reinterpret_cast<float2*>(sm + OFF_STAT);

    int tid = threadIdx.x;
    int lane = tid & 31;
    int warp = tid >> 5;
    int mw = warp & 7;          // M-tile
    int nh = warp >> 3;         // N-half (0/1)
    int v0 = blockIdx.x * 128;
    int m0 = mw * 16;

    if (tid < 128) {
        int v = min(v0 + tid, nN - 1);
        inorm_s[tid] = __ldg(&g_norm_in[v]);
    }
    __syncthreads();

    uint32_t aRow = (uint32_t)(m0 + (lane & 15)) * ROWB + (uint32_t)(lane >> 4) * 16;
    uint32_t bRow = (uint32_t)((lane & 7) + ((lane >> 3) & 1) * 8) * ROWB
                    + (uint32_t)(lane >> 4) * 16 + (uint32_t)nh * 128;
    uint32_t aHi = sbase + OFF_AHI + aRow, aLo = sbase + OFF_ALO + aRow;
    uint32_t bHi = sbase + OFF_BHI + bRow, bLo = sbase + OFF_BLO + bRow;

    float acc[8][4];
#pragma unroll
    for (int nt = 0; nt < 8; nt++)
#pragma unroll
        for (int e = 0; e < 4; e++) acc[nt][e] = 0.f;

    const float* ga = reinterpret_cast<const float*>(g_agg4);

    for (int c = 0; c < 2; c++) {
        // ---- stage A chunk (x cols 128c..) as bf16 hi/lo ----
        for (int i = tid; i < 4096; i += 512) {
            int m = i >> 5, j = i & 31;
            int v = min(v0 + m, nN - 1);
            float4 xv;
            if (c == 0) {
                xv = *reinterpret_cast<const float4*>(ga + (size_t)v * DIM + 4 * j);
                float t = inorm_s[m];
                xv.x *= t; xv.y *= t; xv.z *= t; xv.w *= t;
            } else {
                xv = *reinterpret_cast<const float4*>(feat + (size_t)v * DIM + 4 * j);
            }
            __nv_bfloat162 h0 = __floats2bfloat162_rn(xv.x, xv.y);
            __nv_bfloat162 h1 = __floats2bfloat162_rn(xv.z, xv.w);
            __nv_bfloat162 l0 = __floats2bfloat162_rn(xv.x - __low2float(h0),
                                                      xv.y - __high2float(h0));
            __nv_bfloat162 l1 = __floats2bfloat162_rn(xv.z - __low2float(h1),
                                                      xv.w - __high2float(h1));
            uint32_t off = (uint32_t)m * ROWB + 8 * j;
            *reinterpret_cast<__nv_bfloat162*>(sm + OFF_AHI + off)     = h0;
            *reinterpret_cast<__nv_bfloat162*>(sm + OFF_AHI + off + 4) = h1;
            *reinterpret_cast<__nv_bfloat162*>(sm + OFF_ALO + off)     = l0;
            *reinterpret_cast<__nv_bfloat162*>(sm + OFF_ALO + off + 4) = l1;
        }
        // ---- stage B chunk: plain 16B copies of pre-split W ----
        const uint4* whiv = reinterpret_cast<const uint4*>(g_whi + c * 128 * 128);
        const uint4* wlov = reinterpret_cast<const uint4*>(g_wlo + c * 128 * 128);
        for (int i = tid; i < 2048; i += 512) {
            int k = i >> 4, j = i & 15;
            uint32_t off = (uint32_t)k * ROWB + 16 * j;
            *reinterpret_cast<uint4*>(sm + OFF_BHI + off) = __ldg(whiv + i);
            *reinterpret_cast<uint4*>(sm + OFF_BLO + off) = __ldg(wlov + i);
        }
        __syncthreads();

        // ---- mainloop: 8 k-steps; term-major MMA order ----
#pragma unroll
        for (int ks = 0; ks < 8; ks++) {
            uint32_t ah[4], al[4];
            ldmx4(ah, aHi + ks * 32);
            ldmx4(al, aLo + ks * 32);
            uint32_t bh[4][4], bl[4][4];
#pragma unroll
            for (int p = 0; p < 4; p++) {
                ldmx4t(bh[p], bHi + ks * (16 * ROWB) + 32 * p);
                ldmx4t(bl[p], bLo + ks * (16 * ROWB) + 32 * p);
            }
#pragma unroll
            for (int p = 0; p < 4; p++) {
                mma16816(acc[2 * p],     ah, bh[p][0], bh[p][1]);
                mma16816(acc[2 * p + 1], ah, bh[p][2], bh[p][3]);
            }
#pragma unroll
            for (int p = 0; p < 4; p++) {
                mma16816(acc[2 * p],     ah, bl[p][0], bl[p][1]);
                mma16816(acc[2 * p + 1], ah, bl[p][2], bl[p][3]);
            }
#pragma unroll
            for (int p = 0; p < 4; p++) {
                mma16816(acc[2 * p],     al, bh[p][0], bh[p][1]);
                mma16816(acc[2 * p + 1], al, bh[p][2], bh[p][3]);
            }
        }
        __syncthreads();   // smem reuse fence
    }

    // ---- epilogue: bias + split-row LN via smem stats + ReLU ----
    int rq = lane >> 2;
    int cq = (lane & 3) * 2;
    int rA = m0 + rq, rB = rA + 8;
    float tA = inorm_s[rA];
    float tB = inorm_s[rB];

    float s1A = 0.f, s2A = 0.f, s1B = 0.f, s2B = 0.f;
#pragma unroll
    for (int nt = 0; nt < 8; nt++) {
        int col = nh * 64 + nt * 8 + cq;
        float2 bb = *reinterpret_cast<const float2*>(fc_b + col);
        float y0 = acc[nt][0] + tA * bb.x;
        float y1 = acc[nt][1] + tA * bb.y;
        float y2 = acc[nt][2] + tB * bb.x;
        float y3 = acc[nt][3] + tB * bb.y;
        acc[nt][0] = y0; acc[nt][1] = y1; acc[nt][2] = y2; acc[nt][3] = y3;
        s1A += y0 + y1;  s2A += y0 * y0 + y1 * y1;
        s1B += y2 + y3;  s2B += y2 * y2 + y3 * y3;
    }
#pragma unroll
    for (int o = 1; o <= 2; o <<= 1) {
        s1A += __shfl_xor_sync(0xffffffffu, s1A, o);
        s2A += __shfl_xor_sync(0xffffffffu, s2A, o);
        s1B += __shfl_xor_sync(0xffffffffu, s1B, o);
        s2B += __shfl_xor_sync(0xffffffffu, s2B, o);
    }
    if ((lane & 3) == 0) {
        stat_s[rA * 2 + nh] = make_float2(s1A, s2A);
        stat_s[rB * 2 + nh] = make_float2(s1B, s2B);
    }
    __syncthreads();
    float2 pA0 = stat_s[rA * 2], pA1 = stat_s[rA * 2 + 1];
    float2 pB0 = stat_s[rB * 2], pB1 = stat_s[rB * 2 + 1];
    float muA = (pA0.x + pA1.x) * (1.0f / 128.0f);
    float muB = (pB0.x + pB1.x) * (1.0f / 128.0f);
    float rsA = rsqrtf(fmaxf((pA0.y + pA1.y) * (1.0f / 128.0f) - muA * muA, 0.f) + LN_EPS);
    float rsB = rsqrtf(fmaxf((pB0.y + pB1.y) * (1.0f / 128.0f) - muB * muB, 0.f) + LN_EPS);

    int rowA = v0 + rA, rowB = v0 + rB;
    float* oA = out + (size_t)rowA * DIM;
    float* oB = out + (size_t)rowB * DIM;
#pragma unroll
    for (int nt = 0; nt < 8; nt++) {
        int col = nh * 64 + nt * 8 + cq;
        float2 gg = *reinterpret_cast<const float2*>(ln_g + col);
        float2 b2 = *reinterpret_cast<const float2*>(ln_b + col);
        if (rowA < nN) {
            float2 o2;
            o2.x = fmaxf(fmaf((acc[nt][0] - muA) * rsA, gg.x, b2.x), 0.f);
            o2.y = fmaxf(fmaf((acc[nt][1] - muA) * rsA, gg.y, b2.y), 0.f);
            *reinterpret_cast<float2*>(oA + col) = o2;
        }
        if (rowB < nN) {
            float2 o2;
            o2.x = fmaxf(fmaf((acc[nt][2] - muB) * rsB, gg.x, b2.x), 0.f);
            o2.y = fmaxf(fmaf((acc[nt][3] - muB) * rsB, gg.y, b2.y), 0.f);
            *reinterpret_cast<float2*>(oB + col) = o2;
        }
    }
}

// ---------------- launcher -----------------------------------------------------
extern "C" void kernel_launch(void* const* d_in, const int* in_sizes, int n_in,
                              void* d_out, int out_size) {
    const float* feat  = (const float*)d_in[0];
    const int*   src   = (const int*)d_in[1];
    const int*   dst   = (const int*)d_in[2];
    const float* fc_w  = (const float*)d_in[3];
    const float* fc_b  = (const float*)d_in[4];
    const float* res_w = (const float*)d_in[5];
    const float* ln_g  = (const float*)d_in[6];
    const float* ln_b  = (const float*)d_in[7];
    float* out = (float*)d_out;

    int nN = in_sizes[0] / DIM;   // 50000
    int nE = in_sizes[1];         // 600000

    // K0: zero degree counters; K0b: pre-split W
    zero_kernel<<<(nN + 255) / 256, 256>>>(nN);
    wsplit_kernel<<<32, 256>>>(fc_w, res_w);
    // K1: degrees
    degree_kernel<<<(nE + 255) / 256, 256>>>(src, dst, nE);
    // K2: CSR offsets + norms (single block scan)
    scan_kernel<<<1, 1024>>>(nN);
    // K3: counting-sort edges by dst
    fill_kernel<<<(nE + 255) / 256, 256>>>(src, dst, nE);
    // K4: gather-aggregate, warp per dst node (no feature atomics)
    {
        long long threads = (long long)nN * 32;
        int blocks = (int)((threads + 255) / 256);
        aggregate_kernel<<<blocks, 256>>>(feat, nN);
    }
    // K5: HMMA fused GEMM + bias + in_norm scale + residual + LN + ReLU
    {
        const int SMEM = 141824;
        cudaFuncSetAttribute(final_kernel,
                             cudaFuncAttributeMaxDynamicSharedMemorySize, SMEM);
        int blocks = (nN + 127) / 128;   // 391
        final_kernel<<<blocks, 512, SMEM>>>(feat, fc_b, ln_g, ln_b, out, nN);
    }
}